// round 5
// baseline (speedup 1.0000x reference)
#include <cuda_runtime.h>
#include <cstdint>

#define SDIM  16
#define NNODE 256
#define VDIM  64
#define EDIM  64
#define HDIM  16
#define KEDGE 255   // N-1

typedef unsigned long long ull;

// per-node projections, pr stored TRANSPOSED: g_prT[s][e][n]
__device__ float g_prT[SDIM * HDIM * NNODE];
__device__ float g_psb[SDIM * NNODE * HDIM];   // psb[sn][e] = v0@we1[64:128] + be1

__device__ __forceinline__ float fast_tanh(float x) {
    // tanh(x) = 1 - 2/(e^{2x}+1); robust at +/-inf, MUFU-based, ~1e-6 rel err
    float y = __expf(2.0f * x);
    return 1.0f - __fdividef(2.0f, y + 1.0f);
}
__device__ __forceinline__ ull dup2(float t) {
    ull u; asm("mov.b64 %0, {%1, %1};" : "=l"(u) : "f"(t)); return u;
}
__device__ __forceinline__ ull pack2(float a, float b) {
    ull u; asm("mov.b64 %0, {%1, %2};" : "=l"(u) : "f"(a), "f"(b)); return u;
}

// ---------------------------------------------------------------------------
// Kernel A: per-node projections (tiny). one block per (s,n), 64 threads.
// ---------------------------------------------------------------------------
__global__ void __launch_bounds__(64) proj_kernel(
    const float* __restrict__ v0,
    const float* __restrict__ we1, const float* __restrict__ be1)
{
    const int sn  = blockIdx.x;
    const int tid = threadIdx.x;
    __shared__ float vs[VDIM];

    vs[tid] = v0[(size_t)sn * VDIM + tid];
    __syncthreads();

    const int s_idx = sn >> 8;
    const int n_idx = sn & 255;
    if (tid < 16) {
        float a = 0.f;
        #pragma unroll
        for (int e = 0; e < VDIM; e++) a = fmaf(vs[e], we1[e * HDIM + tid], a);
        g_prT[(s_idx * HDIM + tid) * NNODE + n_idx] = a;
    } else if (tid < 32) {
        int j = tid - 16;
        float a = be1[j];
        #pragma unroll
        for (int e = 0; e < VDIM; e++) a = fmaf(vs[e], we1[(VDIM + e) * HDIM + j], a);
        g_psb[sn * HDIM + j] = a;
    }
}

// ---------------------------------------------------------------------------
// Mega kernel: one block per (s,n). Software-pipelined: 4-deep circular LDG
// buffer, one e0 load issued every 2 edge-GEMM iterations, consumed 8 iters
// later -> reads continuously in flight while FFMA2/LDS/STG work proceeds.
// ---------------------------------------------------------------------------
__global__ void __launch_bounds__(256, 3) mega_kernel(
    const float* __restrict__ e0,
    const float* __restrict__ wv1, const float* __restrict__ bv1,
    const float* __restrict__ wv2, const float* __restrict__ bv2,
    const float* __restrict__ we2, const float* __restrict__ be2,
    float* __restrict__ dv_out, float* __restrict__ de_out)
{
    __shared__ union SM {
        struct { ulonglong2 tdup[8][256]; } edge;                    // 32 KB
        struct { float4 part[16][17]; float evs[EDIM]; float hv[HDIM]; } node;
    } sm;
    __shared__ float psb_s[HDIM];

    const int sn  = blockIdx.x;           // s*256 + n  (n is also edge-row i)
    const int s   = sn >> 8;
    const int i   = sn & 255;
    const int tid = threadIdx.x;
    const int w   = tid >> 5;             // warp 0..7
    const int l   = tid & 31;             // lane
    const int c4  = l & 15;               // float4 slot in 64-wide channel dim
    const int r0  = w * 2 + (l >> 4);     // 0..15: row offset within 16-row groups

    const float4* e0p = reinterpret_cast<const float4*>(e0)
                      + (size_t)sn * (KEDGE * EDIM / 4);

    // prologue: fill 4-deep circular buffer (groups 0..3 -> rows 0..63, all valid)
    float4 buf[4];
    #pragma unroll
    for (int u = 0; u < 4; u++)
        buf[u] = __ldcs(&e0p[(u * 16 + r0) * 16 + c4]);

    if (tid < 4)
        reinterpret_cast<float4*>(psb_s)[tid] =
            reinterpret_cast<const float4*>(g_psb + sn * HDIM)[tid];

    // lane-private packed weights: channels 2l, 2l+1 for all 16 h-dims
    ull wr[16], B;
    #pragma unroll
    for (int e = 0; e < HDIM; e++) {
        float2 wf = reinterpret_cast<const float2*>(we2)[e * 32 + l];
        wr[e] = pack2(wf.x, wf.y);
    }
    {
        float2 bf = reinterpret_cast<const float2*>(be2)[l];
        B = pack2(bf.x, bf.y);
    }
    __syncthreads();                       // psb_s visible

    // --- tanh table: thread k computes t[k][0..15], stores duplicated pairs ---
    if (tid < KEDGE) {
        const int j = tid + (tid >= i);    // skip diagonal
        const float* prb = g_prT + s * HDIM * NNODE + j;
        #pragma unroll
        for (int m = 0; m < 8; m++) {
            float x0 = __ldg(prb + (2 * m    ) * NNODE) + psb_s[2 * m    ];
            float x1 = __ldg(prb + (2 * m + 1) * NNODE) + psb_s[2 * m + 1];
            sm.edge.tdup[m][tid] =
                make_ulonglong2(dup2(fast_tanh(x0)), dup2(fast_tanh(x1)));
        }
    }
    __syncthreads();                       // table ready

    ull accA = 0, accB = 0;                // packed e0 partial sums
    float* outp = de_out + (size_t)sn * KEDGE * VDIM + l * 2;

#define EDGE_ITER(IT) do {                                                     \
        const int k_ = (IT) * 8 + w;                                           \
        if (k_ < KEDGE) {                                                      \
            ull A0 = B, A1 = 0;                                                \
            _Pragma("unroll")                                                  \
            for (int m = 0; m < 4; m++) {                                      \
                ulonglong2 tt = sm.edge.tdup[m][k_];                           \
                asm("fma.rn.f32x2 %0, %1, %2, %0;" : "+l"(A0) : "l"(wr[2*m  ]), "l"(tt.x)); \
                asm("fma.rn.f32x2 %0, %1, %2, %0;" : "+l"(A0) : "l"(wr[2*m+1]), "l"(tt.y)); \
            }                                                                  \
            _Pragma("unroll")                                                  \
            for (int m = 4; m < 8; m++) {                                      \
                ulonglong2 tt = sm.edge.tdup[m][k_];                           \
                asm("fma.rn.f32x2 %0, %1, %2, %0;" : "+l"(A1) : "l"(wr[2*m  ]), "l"(tt.x)); \
                asm("fma.rn.f32x2 %0, %1, %2, %0;" : "+l"(A1) : "l"(wr[2*m+1]), "l"(tt.y)); \
            }                                                                  \
            asm("add.rn.f32x2 %0, %0, %1;" : "+l"(A0) : "l"(A1));              \
            float2 o_;                                                         \
            asm("mov.b64 {%0, %1}, %2;" : "=f"(o_.x), "=f"(o_.y) : "l"(A0));   \
            __stcs(reinterpret_cast<float2*>(outp + (size_t)k_ * VDIM), o_);   \
        }                                                                      \
    } while (0)

    // --- pipelined main loop: 16 groups; per group 2 edge iters + 1 LDG ---
    #pragma unroll 1
    for (int gb = 0; gb < 16; gb += 4) {
        #pragma unroll
        for (int u = 0; u < 4; u++) {
            const int g = gb + u;
            EDGE_ITER(2 * g);
            EDGE_ITER(2 * g + 1);
            // consume buf[u] (group g), then refill with group g+4
            {
                float4 v = buf[u];
                const int r = g * 16 + r0;
                if (r < KEDGE) {
                    ull va = pack2(v.x, v.y), vb = pack2(v.z, v.w);
                    asm("add.rn.f32x2 %0, %0, %1;" : "+l"(accA) : "l"(va));
                    asm("add.rn.f32x2 %0, %0, %1;" : "+l"(accB) : "l"(vb));
                }
                const int rn = r + 64;
                if (rn < KEDGE) buf[u] = __ldcs(&e0p[rn * 16 + c4]);
            }
        }
    }
#undef EDGE_ITER

    // --- node epilogue: reduce partials (reuse tdup smem), tiny MLPs ---
    float4 acc;
    asm("mov.b64 {%0, %1}, %2;" : "=f"(acc.x), "=f"(acc.y) : "l"(accA));
    asm("mov.b64 {%0, %1}, %2;" : "=f"(acc.z), "=f"(acc.w) : "l"(accB));

    __syncthreads();                       // everyone done reading tdup
    sm.node.part[r0][c4] = acc;            // 16 owners x 16 c4 slots
    __syncthreads();

    if (tid < 16) {
        float4 a = sm.node.part[0][tid];
        #pragma unroll
        for (int g = 1; g < 16; g++) {
            float4 p = sm.node.part[g][tid];
            a.x += p.x; a.y += p.y; a.z += p.z; a.w += p.w;
        }
        reinterpret_cast<float4*>(sm.node.evs)[tid] = a;
    }
    __syncthreads();

    if (tid < 16) {
        float a = bv1[tid];
        #pragma unroll
        for (int e = 0; e < EDIM; e++) a = fmaf(sm.node.evs[e], wv1[e * HDIM + tid], a);
        sm.node.hv[tid] = fast_tanh(a);
    }
    __syncthreads();

    if (tid < VDIM) {
        float a = bv2[tid];
        #pragma unroll
        for (int j = 0; j < HDIM; j++) a = fmaf(sm.node.hv[j], wv2[j * VDIM + tid], a);
        dv_out[(size_t)sn * VDIM + tid] = a;
    }
}

// ---------------------------------------------------------------------------
// inputs (metadata order): t, v0, e0, wv1, bv1, wv2, bv2, we1, be1, we2, be2,
//                          recv_idx, send_idx (idx arrays unused: analytic)
// output: dv (S,N,V) followed by de (S,N,N-1,E)
// ---------------------------------------------------------------------------
extern "C" void kernel_launch(void* const* d_in, const int* in_sizes, int n_in,
                              void* d_out, int out_size)
{
    const float* v0  = (const float*)d_in[1];
    const float* e0  = (const float*)d_in[2];
    const float* wv1 = (const float*)d_in[3];
    const float* bv1 = (const float*)d_in[4];
    const float* wv2 = (const float*)d_in[5];
    const float* bv2 = (const float*)d_in[6];
    const float* we1 = (const float*)d_in[7];
    const float* be1 = (const float*)d_in[8];
    const float* we2 = (const float*)d_in[9];
    const float* be2 = (const float*)d_in[10];

    float* dv_out = (float*)d_out;
    float* de_out = dv_out + (size_t)SDIM * NNODE * VDIM;

    proj_kernel<<<SDIM * NNODE, 64>>>(v0, we1, be1);
    mega_kernel<<<SDIM * NNODE, 256>>>(e0, wv1, bv1, wv2, bv2, we2, be2,
                                       dv_out, de_out);
}

// round 6
// speedup vs baseline: 1.1590x; 1.1590x over previous
#include <cuda_runtime.h>
#include <cstdint>

#define SDIM  16
#define NNODE 256
#define VDIM  64
#define EDIM  64
#define HDIM  16
#define KEDGE 255   // N-1

typedef unsigned long long ull;

// per-node projections, pr stored TRANSPOSED: g_prT[s][e][n]
__device__ float g_prT[SDIM * HDIM * NNODE];
__device__ float g_psb[SDIM * NNODE * HDIM];   // psb[sn][e] = v0@we1[64:128] + be1

__device__ __forceinline__ float fast_tanh(float x) {
    // tanh(x) = 1 - 2/(e^{2x}+1); robust at +/-inf, MUFU-based, ~1e-6 rel err
    float y = __expf(2.0f * x);
    return 1.0f - __fdividef(2.0f, y + 1.0f);
}
__device__ __forceinline__ ull pack2(float a, float b) {
    ull u; asm("mov.b64 %0, {%1, %2};" : "=l"(u) : "f"(a), "f"(b)); return u;
}

// ---------------------------------------------------------------------------
// Kernel A: per-node projections (tiny). one block per (s,n), 64 threads.
// ---------------------------------------------------------------------------
__global__ void __launch_bounds__(64) proj_kernel(
    const float* __restrict__ v0,
    const float* __restrict__ we1, const float* __restrict__ be1)
{
    const int sn  = blockIdx.x;
    const int tid = threadIdx.x;
    __shared__ float vs[VDIM];

    vs[tid] = v0[(size_t)sn * VDIM + tid];
    __syncthreads();

    const int s_idx = sn >> 8;
    const int n_idx = sn & 255;
    if (tid < 16) {
        float a = 0.f;
        #pragma unroll
        for (int e = 0; e < VDIM; e++) a = fmaf(vs[e], we1[e * HDIM + tid], a);
        g_prT[(s_idx * HDIM + tid) * NNODE + n_idx] = a;
    } else if (tid < 32) {
        int j = tid - 16;
        float a = be1[j];
        #pragma unroll
        for (int e = 0; e < VDIM; e++) a = fmaf(vs[e], we1[(VDIM + e) * HDIM + j], a);
        g_psb[sn * HDIM + j] = a;
    }
}

// ---------------------------------------------------------------------------
// Mega kernel: one block per (s,n), 4 CTAs/SM.
//  t-table stored in NATURAL order (no duplication, 16KB): tt2[m][k] holds
//  (t[4m..4m+3]) as two packed f32x2. Lane owns ONE channel; weights are
//  h-PAIR packed (8 ull = 16 regs): out[c] = hadd( sum_m wd[m]*f32x2 tpair ).
//  Warp w: edge slot a=w>>1 (k = 16g+4q+a), channel half h=w&1, c = 32h+lane.
//  e0 reads pipelined in a 4-deep register buffer (1 LDG per 4 edge iters).
// ---------------------------------------------------------------------------
__global__ void __launch_bounds__(256, 4) mega_kernel(
    const float* __restrict__ e0,
    const float* __restrict__ wv1, const float* __restrict__ bv1,
    const float* __restrict__ wv2, const float* __restrict__ bv2,
    const float* __restrict__ we2, const float* __restrict__ be2,
    float* __restrict__ dv_out, float* __restrict__ de_out)
{
    __shared__ union SM {
        ulonglong2 tt2[4][256];                                      // 16 KB
        struct { float4 part[16][17]; float evs[EDIM]; float hv[HDIM]; } node;
    } sm;
    __shared__ float psb_s[HDIM];

    const int sn  = blockIdx.x;           // s*256 + n  (n is also edge-row i)
    const int s   = sn >> 8;
    const int i   = sn & 255;
    const int tid = threadIdx.x;
    const int w   = tid >> 5;             // warp 0..7
    const int l   = tid & 31;             // lane
    const int c4  = l & 15;               // float4 slot in 64-wide channel dim
    const int r0  = w * 2 + (l >> 4);     // 0..15: row offset within 16-row groups
    const int a   = w >> 1;               // edge slot 0..3
    const int c   = ((w & 1) << 5) + l;   // owned output channel 0..63

    const float4* e0p = reinterpret_cast<const float4*>(e0)
                      + (size_t)sn * (KEDGE * EDIM / 4);

    // prologue: fill 4-deep circular buffer (rows 0..63, all valid)
    float4 buf[4];
    #pragma unroll
    for (int u = 0; u < 4; u++)
        buf[u] = __ldcs(&e0p[(u * 16 + r0) * 16 + c4]);

    if (tid < 4)
        reinterpret_cast<float4*>(psb_s)[tid] =
            reinterpret_cast<const float4*>(g_psb + sn * HDIM)[tid];

    // lane weights: h-pair packed for channel c -> 8 ull (16 regs)
    ull wd[8];
    #pragma unroll
    for (int m = 0; m < 8; m++)
        wd[m] = pack2(we2[(2 * m) * VDIM + c], we2[(2 * m + 1) * VDIM + c]);
    const float bias = be2[c];
    __syncthreads();                       // psb_s visible

    // --- tanh table: thread k computes t[k][0..15] in natural order ---
    if (tid < KEDGE) {
        const int j = tid + (tid >= i);    // skip diagonal
        const float* prb = g_prT + s * HDIM * NNODE + j;
        #pragma unroll
        for (int m = 0; m < 4; m++) {
            float t0 = fast_tanh(__ldg(prb + (4 * m    ) * NNODE) + psb_s[4 * m    ]);
            float t1 = fast_tanh(__ldg(prb + (4 * m + 1) * NNODE) + psb_s[4 * m + 1]);
            float t2 = fast_tanh(__ldg(prb + (4 * m + 2) * NNODE) + psb_s[4 * m + 2]);
            float t3 = fast_tanh(__ldg(prb + (4 * m + 3) * NNODE) + psb_s[4 * m + 3]);
            sm.tt2[m][tid] = make_ulonglong2(pack2(t0, t1), pack2(t2, t3));
        }
    }
    __syncthreads();                       // table ready

    ull accA = 0, accB = 0;                // packed e0 partial sums
    float* outp = de_out + (size_t)sn * KEDGE * VDIM + c;

#define EDGE_ITER(K) do {                                                      \
        const int k_ = (K);                                                    \
        if (k_ < KEDGE) {                                                      \
            ull A0 = 0, A1 = 0;                                                \
            _Pragma("unroll")                                                  \
            for (int m = 0; m < 4; m++) {                                      \
                ulonglong2 tp = sm.tt2[m][k_];          /* broadcast LDS.128 */\
                asm("fma.rn.f32x2 %0, %1, %2, %0;" : "+l"(A0) : "l"(wd[2*m  ]), "l"(tp.x)); \
                asm("fma.rn.f32x2 %0, %1, %2, %0;" : "+l"(A1) : "l"(wd[2*m+1]), "l"(tp.y)); \
            }                                                                  \
            asm("add.rn.f32x2 %0, %0, %1;" : "+l"(A0) : "l"(A1));              \
            float lo_, hi_;                                                    \
            asm("mov.b64 {%0, %1}, %2;" : "=f"(lo_), "=f"(hi_) : "l"(A0));     \
            __stcs(outp + (size_t)k_ * VDIM, lo_ + hi_ + bias);                \
        }                                                                      \
    } while (0)

    // --- pipelined main loop: 16 groups; per group 4 edge iters + 1 LDG ---
    #pragma unroll 1
    for (int gb = 0; gb < 16; gb += 4) {
        #pragma unroll
        for (int u = 0; u < 4; u++) {
            const int g = gb + u;
            EDGE_ITER(16 * g      + a);
            EDGE_ITER(16 * g + 4  + a);
            EDGE_ITER(16 * g + 8  + a);
            EDGE_ITER(16 * g + 12 + a);
            // consume buf[u] (row group g), then refill with group g+4
            {
                float4 v = buf[u];
                const int r = g * 16 + r0;
                if (r < KEDGE) {
                    ull va = pack2(v.x, v.y), vb = pack2(v.z, v.w);
                    asm("add.rn.f32x2 %0, %0, %1;" : "+l"(accA) : "l"(va));
                    asm("add.rn.f32x2 %0, %0, %1;" : "+l"(accB) : "l"(vb));
                }
                const int rn = r + 64;
                if (rn < KEDGE) buf[u] = __ldcs(&e0p[rn * 16 + c4]);
            }
        }
    }
#undef EDGE_ITER

    // --- node epilogue: reduce partials (reuse smem), tiny MLPs ---
    float4 acc;
    asm("mov.b64 {%0, %1}, %2;" : "=f"(acc.x), "=f"(acc.y) : "l"(accA));
    asm("mov.b64 {%0, %1}, %2;" : "=f"(acc.z), "=f"(acc.w) : "l"(accB));

    __syncthreads();                       // everyone done reading tt2
    sm.node.part[r0][c4] = acc;            // 16 owners x 16 c4 slots
    __syncthreads();

    if (tid < 16) {
        float4 p4 = sm.node.part[0][tid];
        #pragma unroll
        for (int g = 1; g < 16; g++) {
            float4 p = sm.node.part[g][tid];
            p4.x += p.x; p4.y += p.y; p4.z += p.z; p4.w += p.w;
        }
        reinterpret_cast<float4*>(sm.node.evs)[tid] = p4;
    }
    __syncthreads();

    if (tid < 16) {
        float v = bv1[tid];
        #pragma unroll
        for (int e = 0; e < EDIM; e++) v = fmaf(sm.node.evs[e], wv1[e * HDIM + tid], v);
        sm.node.hv[tid] = fast_tanh(v);
    }
    __syncthreads();

    if (tid < VDIM) {
        float v = bv2[tid];
        #pragma unroll
        for (int j = 0; j < HDIM; j++) v = fmaf(sm.node.hv[j], wv2[j * VDIM + tid], v);
        dv_out[(size_t)sn * VDIM + tid] = v;
    }
}

// ---------------------------------------------------------------------------
// inputs (metadata order): t, v0, e0, wv1, bv1, wv2, bv2, we1, be1, we2, be2,
//                          recv_idx, send_idx (idx arrays unused: analytic)
// output: dv (S,N,V) followed by de (S,N,N-1,E)
// ---------------------------------------------------------------------------
extern "C" void kernel_launch(void* const* d_in, const int* in_sizes, int n_in,
                              void* d_out, int out_size)
{
    const float* v0  = (const float*)d_in[1];
    const float* e0  = (const float*)d_in[2];
    const float* wv1 = (const float*)d_in[3];
    const float* bv1 = (const float*)d_in[4];
    const float* wv2 = (const float*)d_in[5];
    const float* bv2 = (const float*)d_in[6];
    const float* we1 = (const float*)d_in[7];
    const float* be1 = (const float*)d_in[8];
    const float* we2 = (const float*)d_in[9];
    const float* be2 = (const float*)d_in[10];

    float* dv_out = (float*)d_out;
    float* de_out = dv_out + (size_t)SDIM * NNODE * VDIM;

    proj_kernel<<<SDIM * NNODE, 64>>>(v0, we1, be1);
    mega_kernel<<<SDIM * NNODE, 256>>>(e0, wv1, bv1, wv2, bv2, we2, be2,
                                       dv_out, de_out);
}